// round 15
// baseline (speedup 1.0000x reference)
#include <cuda_runtime.h>
#include <cstdint>
#include <math.h>

#define NB 8
#define NC 512
#define NT 2048
#define NGRP 32
#define NH 8
#define CH 64

// scratch (no cudaMalloc allowed)
__device__ float g_xn[NB * NC * NT];            // 32 MB
__device__ float g_q[NB * NH * NT * CH];        // 32 MB  [b,h,t,c] (tf32 bits)
__device__ float g_k[NB * NH * NT * CH];        // 32 MB  [b,h,t,c] (tf32 bits)
__device__ float g_v[NB * NH * CH * NT];        // 32 MB  [b,h,c,t] (tf32 bits)
__device__ float g_attn[NB * NC * NT];          // 32 MB  [b,c,t]
__device__ float g_an[NB * NC * NT];            // 32 MB

// ---------------------------------------------------------------------------
// helpers
// ---------------------------------------------------------------------------
__device__ __forceinline__ uint32_t cvt_tf32(float f) {
    uint32_t u;
    asm("cvt.rna.tf32.f32 %0, %1;" : "=r"(u) : "f"(f));
    return u;
}
__device__ __forceinline__ float tf32f(float f) {
    return __uint_as_float(cvt_tf32(f));
}
__device__ __forceinline__ float ex2f(float x) {
    float r;
    asm("ex2.approx.ftz.f32 %0, %1;" : "=f"(r) : "f"(x));
    return r;
}
// D += A @ B  (m16n8k8 tf32)
__device__ __forceinline__ void mma8(float* d, const uint32_t* a, uint32_t b0, uint32_t b1) {
    asm volatile(
        "mma.sync.aligned.m16n8k8.row.col.f32.tf32.tf32.f32 "
        "{%0,%1,%2,%3}, {%4,%5,%6,%7}, {%8,%9}, {%0,%1,%2,%3};"
        : "+f"(d[0]), "+f"(d[1]), "+f"(d[2]), "+f"(d[3])
        : "r"(a[0]), "r"(a[1]), "r"(a[2]), "r"(a[3]), "r"(b0), "r"(b1));
}
__device__ __forceinline__ uint32_t smem_u32(const void* p) {
    uint32_t r;
    asm("{ .reg .u64 t; cvta.to.shared.u64 t, %1; cvt.u32.u64 %0, t; }"
        : "=r"(r) : "l"(p));
    return r;
}
__device__ __forceinline__ void cpa16(uint32_t s, const void* g) {
    asm volatile("cp.async.ca.shared.global [%0], [%1], 16;" :: "r"(s), "l"(g));
}
#define CP_COMMIT() asm volatile("cp.async.commit_group;" ::: "memory")
#define CP_WAIT(n)  asm volatile("cp.async.wait_group %0;" :: "n"(n) : "memory")

// ---------------------------------------------------------------------------
// GroupNorm: one block per (batch, group). group = 16 channels x 2048 T.
// ---------------------------------------------------------------------------
__global__ void __launch_bounds__(256) gn_kernel(const float* __restrict__ x,
                                                 const float* __restrict__ gamma,
                                                 const float* __restrict__ beta,
                                                 float* __restrict__ y)
{
    __shared__ float rs[256], rq[256];
    const int bg = blockIdx.x;
    const int b = bg >> 5, g = bg & 31;
    const size_t base = ((size_t)b * NC + g * 16) * NT;
    const int n = 16 * NT;

    float s = 0.f, q = 0.f;
    for (int i = threadIdx.x * 4; i < n; i += 256 * 4) {
        float4 v = *(const float4*)(x + base + i);
        s += v.x + v.y + v.z + v.w;
        q += v.x * v.x + v.y * v.y + v.z * v.z + v.w * v.w;
    }
    rs[threadIdx.x] = s; rq[threadIdx.x] = q;
    __syncthreads();
    for (int off = 128; off > 0; off >>= 1) {
        if (threadIdx.x < off) {
            rs[threadIdx.x] += rs[threadIdx.x + off];
            rq[threadIdx.x] += rq[threadIdx.x + off];
        }
        __syncthreads();
    }
    const float mean = rs[0] / (float)n;
    const float var  = rq[0] / (float)n - mean * mean;
    const float inv  = rsqrtf(var + 1e-5f);

    for (int i = threadIdx.x * 4; i < n; i += 256 * 4) {
        const int c = g * 16 + (i >> 11);
        const float ga = gamma[c], be = beta[c];
        float4 v = *(const float4*)(x + base + i);
        float4 o;
        o.x = (v.x - mean) * inv * ga + be;
        o.y = (v.y - mean) * inv * ga + be;
        o.z = (v.z - mean) * inv * ga + be;
        o.w = (v.w - mean) * inv * ga + be;
        *(float4*)(y + base + i) = o;
    }
}

// ---------------------------------------------------------------------------
// tf32 mma.sync GEMM: C = W[M,K=512] @ X[b][K,N] (+bias, routed epilogue).
// CTA tile 128x128, BK=16, 8 warps (4m x 2n), warp tile 32x64.
// MODE 0: proj  -> out[b][m][n] = C + bias[m] + res[b][m][n]   (fp32)
// MODE 1: qkv   -> tf32-rounded Q/K [bh][t][c] (Q scaled 1/8), V [bh][c][t]
// ---------------------------------------------------------------------------
#define AST 17
#define CST 132

template <int MODE>
__global__ void __launch_bounds__(256) tf32_gemm_kernel(
    const float* __restrict__ W, const float* __restrict__ X,
    const float* __restrict__ bias, const float* __restrict__ res,
    float* __restrict__ Co, float* __restrict__ Ko, float* __restrict__ Vo)
{
    extern __shared__ char smraw[];
    uint32_t* As = (uint32_t*)smraw;            // [128][AST]
    uint32_t* Bs = As + 128 * AST;              // [128][AST]
    float*    Cst = (float*)smraw;              // [128][CST] (epilogue alias)

    const int K = NC, N = NT;
    const int batch = blockIdx.z;
    const float* Xb = X + (size_t)batch * K * N;

    const int tid = threadIdx.x;
    const int w = tid >> 5, lane = tid & 31;
    const int g = lane >> 2, qd = lane & 3;
    const int wm = w >> 1, wn = w & 1;
    const int m0 = blockIdx.y * 128;
    const int n0 = blockIdx.x * 128;

    float acc[2][8][4] = {};

    for (int k0 = 0; k0 < K; k0 += 16) {
        // W tile [128 m][16 k] -> As[m][k]
        {
            const int row = tid >> 1;
            const int f0 = (tid & 1) * 8;
            const float* src = W + (size_t)(m0 + row) * K + k0 + f0;
            float4 v0 = *(const float4*)(src);
            float4 v1 = *(const float4*)(src + 4);
            uint32_t* d = As + row * AST + f0;
            d[0] = cvt_tf32(v0.x); d[1] = cvt_tf32(v0.y);
            d[2] = cvt_tf32(v0.z); d[3] = cvt_tf32(v0.w);
            d[4] = cvt_tf32(v1.x); d[5] = cvt_tf32(v1.y);
            d[6] = cvt_tf32(v1.z); d[7] = cvt_tf32(v1.w);
        }
        // X tile [16 k][128 n] -> Bs[n][k] (transposed)
        {
            const int kk = tid >> 4;
            const int nb = (tid & 15) * 8;
            const float* src = Xb + (size_t)(k0 + kk) * N + n0 + nb;
            float4 v0 = *(const float4*)(src);
            float4 v1 = *(const float4*)(src + 4);
            uint32_t* d = Bs + nb * AST + kk;
            d[0 * AST] = cvt_tf32(v0.x); d[1 * AST] = cvt_tf32(v0.y);
            d[2 * AST] = cvt_tf32(v0.z); d[3 * AST] = cvt_tf32(v0.w);
            d[4 * AST] = cvt_tf32(v1.x); d[5 * AST] = cvt_tf32(v1.y);
            d[6 * AST] = cvt_tf32(v1.z); d[7 * AST] = cvt_tf32(v1.w);
        }
        __syncthreads();

#pragma unroll
        for (int ks = 0; ks < 2; ks++) {
            uint32_t av[2][4];
#pragma unroll
            for (int mt = 0; mt < 2; mt++) {
                const uint32_t* a0 = As + (wm * 32 + mt * 16 + g) * AST + ks * 8 + qd;
                const uint32_t* a1 = a0 + 8 * AST;
                av[mt][0] = a0[0]; av[mt][1] = a1[0];
                av[mt][2] = a0[4]; av[mt][3] = a1[4];
            }
#pragma unroll
            for (int nt = 0; nt < 8; nt++) {
                const uint32_t* bp = Bs + (wn * 64 + nt * 8 + g) * AST + ks * 8 + qd;
                const uint32_t b0 = bp[0], b1 = bp[4];
                mma8(acc[0][nt], av[0], b0, b1);
                mma8(acc[1][nt], av[1], b0, b1);
            }
        }
        __syncthreads();
    }

    // stage C into smem (aliased over As/Bs; guarded by syncthreads above)
#pragma unroll
    for (int mt = 0; mt < 2; mt++)
#pragma unroll
        for (int nt = 0; nt < 8; nt++) {
            float* c0 = Cst + (wm * 32 + mt * 16 + g) * CST + wn * 64 + nt * 8 + 2 * qd;
            c0[0] = acc[mt][nt][0];
            c0[1] = acc[mt][nt][1];
            c0[8 * CST] = acc[mt][nt][2];
            c0[8 * CST + 1] = acc[mt][nt][3];
        }
    __syncthreads();

    if (MODE == 0) {
        // proj: out[b][m0+m][n0+t] = C + bias + residual
#pragma unroll
        for (int i = 0; i < 16; i++) {
            const int idx = tid + i * 256;
            const int m = idx >> 5, t4 = (idx & 31) * 4;
            const float bv = bias[m0 + m];
            float4 c = *(const float4*)(Cst + m * CST + t4);
            const size_t go = ((size_t)batch * NC + m0 + m) * NT + n0 + t4;
            float4 r = *(const float4*)(res + go);
            c.x += bv + r.x; c.y += bv + r.y; c.z += bv + r.z; c.w += bv + r.w;
            *(float4*)(Co + go) = c;
        }
    } else {
        // qkv routing: tf32 rounding applied here (Q scaled 1/8), float4 stores
#pragma unroll
        for (int hh = 0; hh < 2; hh++) {
            const int mbase = m0 + hh * 64;
            const int h = mbase / 192;
            const int r = mbase % 192;
            const int seg = r >> 6;                 // 0=q 1=k 2=v
            const int bh = batch * NH + h;
            if (seg == 2) {
                // V: [bh][c][t], coalesced along t
#pragma unroll
                for (int i = 0; i < 8; i++) {
                    const int idx = tid + i * 256;
                    const int c = idx >> 5, t4 = (idx & 31) * 4;
                    const float bv = bias[mbase + c];
                    const float* s = Cst + (hh * 64 + c) * CST + t4;
                    float4 v;
                    v.x = tf32f(s[0] + bv); v.y = tf32f(s[1] + bv);
                    v.z = tf32f(s[2] + bv); v.w = tf32f(s[3] + bv);
                    *(float4*)(Vo + ((size_t)bh * CH + c) * NT + n0 + t4) = v;
                }
            } else {
                // Q/K: [bh][t][c], coalesced along c; Q scaled by 1/8
                const float sc = (seg == 0) ? 0.125f : 1.0f;
                float* dst = (seg ? Ko : Co) + (size_t)bh * NT * CH;
#pragma unroll
                for (int i = 0; i < 8; i++) {
                    const int idx = tid + i * 256;
                    const int t = idx >> 4, cc = (idx & 15) * 4;
                    float4 v;
                    v.x = tf32f((Cst[(hh * 64 + cc + 0) * CST + t] + bias[mbase + cc + 0]) * sc);
                    v.y = tf32f((Cst[(hh * 64 + cc + 1) * CST + t] + bias[mbase + cc + 1]) * sc);
                    v.z = tf32f((Cst[(hh * 64 + cc + 2) * CST + t] + bias[mbase + cc + 2]) * sc);
                    v.w = tf32f((Cst[(hh * 64 + cc + 3) * CST + t] + bias[mbase + cc + 3]) * sc);
                    *(float4*)(dst + (size_t)(n0 + t) * CH + cc) = v;
                }
            }
        }
    }
}

#define GEMM_SMEM (128 * CST * 4)

// ---------------------------------------------------------------------------
// tf32 mma.sync flash attention; 4 warps x 32 queries = 128-query CTA,
// 2 CTAs/SM co-resident (smem ~105 KB, 128 threads). Per-warp structure
// identical to the R12 kernel (2 m-tiles amortize each B-fragment).
// cp.async double-buffered 64-key tiles; inputs pre-rounded tf32 bits.
// ---------------------------------------------------------------------------
#define SQ 68
#define SV 68
#define QS_OFF 0u
#define K0_OFF 34816u
#define K1_OFF 52224u
#define V0_OFF 69632u
#define V1_OFF 87040u
#define LS_OFF 104448u
#define ATT_SMEM (LS_OFF + 640u)
#define NTILE 32
#define L2E 1.4426950408889634f

__global__ void __launch_bounds__(128, 2) attn_mma_kernel(const float* __restrict__ Qg_,
                                                          const float* __restrict__ Kg_,
                                                          const float* __restrict__ Vg_,
                                                          float* __restrict__ out)
{
    extern __shared__ char smem[];
    const uint32_t sb = smem_u32(smem);
    uint32_t* Qs  = (uint32_t*)(smem + QS_OFF);
    float*    Ls  = (float*)(smem + LS_OFF);
    float*    Osm = (float*)(smem + QS_OFF);     // epilogue reuse of Q area

    const int tid = threadIdx.x;
    const int w = tid >> 5, lane = tid & 31;
    const int g = lane >> 2, qd = lane & 3;
    const int bh = blockIdx.y;
    const int b = bh >> 3, h = bh & 7;
    const int t0 = blockIdx.x * 128;

    const float* Qg = Qg_ + ((size_t)bh * NT + t0) * CH;
    const float* Kg = Kg_ + (size_t)bh * NT * CH;
    const float* Vg = Vg_ + (size_t)bh * CH * NT;

    // fill coordinates: 16 threads per row, 16B each (128 threads -> 8 rows/pass)
    const int fr = tid >> 4, fc = (tid & 15) * 4;

    // prologue: Q (128 rows: 16 passes of 8 rows) + K/V tile0, tile1
#pragma unroll
    for (int i = 0; i < 16; i++)
        cpa16(sb + QS_OFF + ((fr + i * 8) * SQ + fc) * 4,
              Qg + (size_t)(fr + i * 8) * CH + fc);
#pragma unroll
    for (int i = 0; i < 8; i++)
        cpa16(sb + K0_OFF + ((fr + i * 8) * SQ + fc) * 4,
              Kg + (size_t)(fr + i * 8) * CH + fc);
#pragma unroll
    for (int i = 0; i < 8; i++)
        cpa16(sb + V0_OFF + ((fr + i * 8) * SV + fc) * 4,
              Vg + (size_t)(fr + i * 8) * NT + fc);
    CP_COMMIT();
#pragma unroll
    for (int i = 0; i < 8; i++)
        cpa16(sb + K1_OFF + ((fr + i * 8) * SQ + fc) * 4,
              Kg + (size_t)(64 + fr + i * 8) * CH + fc);
#pragma unroll
    for (int i = 0; i < 8; i++)
        cpa16(sb + V1_OFF + ((fr + i * 8) * SV + fc) * 4,
              Vg + (size_t)(fr + i * 8) * NT + 64 + fc);
    CP_COMMIT();
    CP_WAIT(1);
    __syncthreads();

    // preload Q A-fragments for this warp's 32 rows (2 m-tiles x 8 k-steps)
    uint32_t qa[2][8][4];
#pragma unroll
    for (int mt = 0; mt < 2; mt++)
#pragma unroll
        for (int ks = 0; ks < 8; ks++) {
            const uint32_t* r0 = Qs + (w * 32 + mt * 16 + g) * SQ + ks * 8 + qd;
            const uint32_t* r1 = r0 + 8 * SQ;
            qa[mt][ks][0] = r0[0];
            qa[mt][ks][1] = r1[0];
            qa[mt][ks][2] = r0[4];
            qa[mt][ks][3] = r1[4];
        }

    float oacc[2][8][4] = {};
    float lr[2][2] = {};
    const int src0 = (lane & ~3) | (qd >> 1);
    const int src2 = src0 + 2;

    for (int st = 0; st < NTILE; st++) {
        const uint32_t* Ks = (const uint32_t*)(smem + ((st & 1) ? K1_OFF : K0_OFF));
        const uint32_t* Vs = (const uint32_t*)(smem + ((st & 1) ? V1_OFF : V0_OFF));

        // S = Q @ K^T : each kb pair feeds both m-tiles
        float sacc[2][8][4] = {};
#pragma unroll
        for (int nt = 0; nt < 8; nt++) {
            const uint32_t* kb = Ks + (nt * 8 + g) * SQ + qd;
#pragma unroll
            for (int ks = 0; ks < 8; ks++) {
                const uint32_t b0 = kb[ks * 8], b1 = kb[ks * 8 + 4];
                mma8(sacc[0][nt], qa[0][ks], b0, b1);
                mma8(sacc[1][nt], qa[1][ks], b0, b1);
            }
        }
        // softmax terms (no max subtraction) + tf32 P fragments
        uint32_t pc[2][8][4];
#pragma unroll
        for (int mt = 0; mt < 2; mt++)
#pragma unroll
            for (int nt = 0; nt < 8; nt++) {
                float p0 = ex2f(sacc[mt][nt][0] * L2E);
                float p1 = ex2f(sacc[mt][nt][1] * L2E);
                float p2 = ex2f(sacc[mt][nt][2] * L2E);
                float p3 = ex2f(sacc[mt][nt][3] * L2E);
                lr[mt][0] += p0 + p1;
                lr[mt][1] += p2 + p3;
                pc[mt][nt][0] = cvt_tf32(p0); pc[mt][nt][1] = cvt_tf32(p1);
                pc[mt][nt][2] = cvt_tf32(p2); pc[mt][nt][3] = cvt_tf32(p3);
            }
        // O += P @ V^T : each vb pair feeds both m-tiles
#pragma unroll
        for (int j = 0; j < 8; j++) {
            uint32_t pa[2][4];
#pragma unroll
            for (int mt = 0; mt < 2; mt++) {
                uint32_t t00 = __shfl_sync(0xFFFFFFFFu, pc[mt][j][0], src0);
                uint32_t t01 = __shfl_sync(0xFFFFFFFFu, pc[mt][j][1], src0);
                uint32_t t10 = __shfl_sync(0xFFFFFFFFu, pc[mt][j][2], src0);
                uint32_t t11 = __shfl_sync(0xFFFFFFFFu, pc[mt][j][3], src0);
                uint32_t t20 = __shfl_sync(0xFFFFFFFFu, pc[mt][j][0], src2);
                uint32_t t21 = __shfl_sync(0xFFFFFFFFu, pc[mt][j][1], src2);
                uint32_t t30 = __shfl_sync(0xFFFFFFFFu, pc[mt][j][2], src2);
                uint32_t t31 = __shfl_sync(0xFFFFFFFFu, pc[mt][j][3], src2);
                pa[mt][0] = (qd & 1) ? t01 : t00;
                pa[mt][1] = (qd & 1) ? t11 : t10;
                pa[mt][2] = (qd & 1) ? t21 : t20;
                pa[mt][3] = (qd & 1) ? t31 : t30;
            }
#pragma unroll
            for (int nt = 0; nt < 8; nt++) {
                const uint32_t* vb = Vs + (nt * 8 + g) * SV + j * 8 + qd;
                const uint32_t v0 = vb[0], v1 = vb[4];
                mma8(oacc[0][nt], pa[0], v0, v1);
                mma8(oacc[1][nt], pa[1], v0, v1);
            }
        }
        __syncthreads();   // done reading buf[st&1]

        if (st + 2 < NTILE) {
            const int s0 = (st + 2) * 64;
            const uint32_t ko = (st & 1) ? K1_OFF : K0_OFF;
            const uint32_t vo = (st & 1) ? V1_OFF : V0_OFF;
#pragma unroll
            for (int i = 0; i < 8; i++)
                cpa16(sb + ko + ((fr + i * 8) * SQ + fc) * 4,
                      Kg + (size_t)(s0 + fr + i * 8) * CH + fc);
#pragma unroll
            for (int i = 0; i < 8; i++)
                cpa16(sb + vo + ((fr + i * 8) * SV + fc) * 4,
                      Vg + (size_t)(fr + i * 8) * NT + s0 + fc);
            CP_COMMIT();
        }
        if (st + 1 < NTILE) {
            if (st + 2 < NTILE) { CP_WAIT(1); } else { CP_WAIT(0); }
            __syncthreads();
        }
    }

    // row-sum reduce across the 4 lanes of each row group; store inverses
#pragma unroll
    for (int mt = 0; mt < 2; mt++) {
        lr[mt][0] += __shfl_xor_sync(0xFFFFFFFFu, lr[mt][0], 1);
        lr[mt][0] += __shfl_xor_sync(0xFFFFFFFFu, lr[mt][0], 2);
        lr[mt][1] += __shfl_xor_sync(0xFFFFFFFFu, lr[mt][1], 1);
        lr[mt][1] += __shfl_xor_sync(0xFFFFFFFFu, lr[mt][1], 2);
        if (qd == 0) {
            Ls[w * 32 + mt * 16 + g]     = 1.0f / lr[mt][0];
            Ls[w * 32 + mt * 16 + 8 + g] = 1.0f / lr[mt][1];
        }
    }
    __syncthreads();   // Q fragments consumed; safe to reuse Q smem for O

    // stage O [q][ch] into reused Q area (per-warp slab, stride SQ)
    float* Ow = Osm + (w * 32) * SQ;
#pragma unroll
    for (int mt = 0; mt < 2; mt++)
#pragma unroll
        for (int nt = 0; nt < 8; nt++) {
            float* c0 = Ow + (mt * 16 + g) * SQ + nt * 8 + 2 * qd;
            c0[0] = oacc[mt][nt][0];
            c0[1] = oacc[mt][nt][1];
            c0[8 * SQ] = oacc[mt][nt][2];
            c0[8 * SQ + 1] = oacc[mt][nt][3];
        }
    __syncwarp();

    // normalized, coalesced write: out[b][h*64+ch][t0 + w*32 + q]
#pragma unroll
    for (int r = 0; r < 16; r++) {
        const int idx = r * 32 + lane;          // 0..511
        const int ch = idx >> 3, q4 = (idx & 7) * 4;
        float4 wv;
        wv.x = Ow[(q4 + 0) * SQ + ch] * Ls[w * 32 + q4 + 0];
        wv.y = Ow[(q4 + 1) * SQ + ch] * Ls[w * 32 + q4 + 1];
        wv.z = Ow[(q4 + 2) * SQ + ch] * Ls[w * 32 + q4 + 2];
        wv.w = Ow[(q4 + 3) * SQ + ch] * Ls[w * 32 + q4 + 3];
        *(float4*)(out + ((size_t)b * NC + h * CH + ch) * NT + t0 + w * 32 + q4) = wv;
    }
}

// ---------------------------------------------------------------------------
extern "C" void kernel_launch(void* const* d_in, const int* in_sizes, int n_in,
                              void* d_out, int out_size)
{
    const float* x     = (const float*)d_in[0];
    const float* g1g   = (const float*)d_in[1];
    const float* g1b   = (const float*)d_in[2];
    const float* wqkv  = (const float*)d_in[3];
    const float* bqkv  = (const float*)d_in[4];
    const float* g2g   = (const float*)d_in[5];
    const float* g2b   = (const float*)d_in[6];
    const float* wproj = (const float*)d_in[7];
    const float* bproj = (const float*)d_in[8];
    float* out = (float*)d_out;

    float *xn, *q, *k, *v, *attn, *an;
    cudaGetSymbolAddress((void**)&xn,   g_xn);
    cudaGetSymbolAddress((void**)&q,    g_q);
    cudaGetSymbolAddress((void**)&k,    g_k);
    cudaGetSymbolAddress((void**)&v,    g_v);
    cudaGetSymbolAddress((void**)&attn, g_attn);
    cudaGetSymbolAddress((void**)&an,   g_an);

    cudaFuncSetAttribute(tf32_gemm_kernel<0>,
                         cudaFuncAttributeMaxDynamicSharedMemorySize, GEMM_SMEM);
    cudaFuncSetAttribute(tf32_gemm_kernel<1>,
                         cudaFuncAttributeMaxDynamicSharedMemorySize, GEMM_SMEM);
    cudaFuncSetAttribute(attn_mma_kernel,
                         cudaFuncAttributeMaxDynamicSharedMemorySize, ATT_SMEM);

    // 1) GroupNorm 1
    gn_kernel<<<NB * NGRP, 256>>>(x, g1g, g1b, xn);

    // 2) QKV conv1x1 (tf32 tensor) with tf32-rounding routing epilogue
    tf32_gemm_kernel<1><<<dim3(NT / 128, 12, NB), 256, GEMM_SMEM>>>(
        wqkv, xn, bqkv, nullptr, q, k, v);

    // 3) tf32 mma.sync flash attention (4 warps, 128q CTA, 2 CTA/SM)
    attn_mma_kernel<<<dim3(NT / 128, NB * NH), 128, ATT_SMEM>>>(q, k, v, attn);

    // 4) GroupNorm 2
    gn_kernel<<<NB * NGRP, 256>>>(attn, g2g, g2b, an);

    // 5) proj conv1x1 (tf32 tensor) + bias + residual
    tf32_gemm_kernel<0><<<dim3(NT / 128, 4, NB), 256, GEMM_SMEM>>>(
        wproj, an, bproj, x, out, nullptr, nullptr);
}

// round 16
// speedup vs baseline: 1.0427x; 1.0427x over previous
#include <cuda_runtime.h>
#include <cstdint>
#include <math.h>

#define NB 8
#define NC 512
#define NT 2048
#define NGRP 32
#define NH 8
#define CH 64

// scratch (no cudaMalloc allowed)
__device__ float g_xn[NB * NC * NT];            // 32 MB
__device__ float g_q[NB * NH * NT * CH];        // 32 MB  [b,h,t,c] tf32, ch-perm
__device__ float g_k[NB * NH * NT * CH];        // 32 MB  [b,h,t,c] tf32, ch+key-perm
__device__ float g_v[NB * NH * CH * NT];        // 32 MB  [b,h,c,t] tf32, key-perm
__device__ float g_attn[NB * NC * NT];          // 32 MB  [b,c,t]
__device__ float g_an[NB * NC * NT];            // 32 MB

// ---------------------------------------------------------------------------
// helpers
// ---------------------------------------------------------------------------
__device__ __forceinline__ uint32_t cvt_tf32(float f) {
    uint32_t u;
    asm("cvt.rna.tf32.f32 %0, %1;" : "=r"(u) : "f"(f));
    return u;
}
__device__ __forceinline__ float tf32f(float f) {
    return __uint_as_float(cvt_tf32(f));
}
__device__ __forceinline__ float ex2f(float x) {
    float r;
    asm("ex2.approx.ftz.f32 %0, %1;" : "=f"(r) : "f"(x));
    return r;
}
// D += A @ B  (m16n8k8 tf32)
__device__ __forceinline__ void mma8(float* d, const uint32_t* a, uint32_t b0, uint32_t b1) {
    asm volatile(
        "mma.sync.aligned.m16n8k8.row.col.f32.tf32.tf32.f32 "
        "{%0,%1,%2,%3}, {%4,%5,%6,%7}, {%8,%9}, {%0,%1,%2,%3};"
        : "+f"(d[0]), "+f"(d[1]), "+f"(d[2]), "+f"(d[3])
        : "r"(a[0]), "r"(a[1]), "r"(a[2]), "r"(a[3]), "r"(b0), "r"(b1));
}
__device__ __forceinline__ uint32_t smem_u32(const void* p) {
    uint32_t r;
    asm("{ .reg .u64 t; cvta.to.shared.u64 t, %1; cvt.u32.u64 %0, t; }"
        : "=r"(r) : "l"(p));
    return r;
}
__device__ __forceinline__ void cpa16(uint32_t s, const void* g) {
    asm volatile("cp.async.ca.shared.global [%0], [%1], 16;" :: "r"(s), "l"(g));
}
#define CP_COMMIT() asm volatile("cp.async.commit_group;" ::: "memory")
#define CP_WAIT(n)  asm volatile("cp.async.wait_group %0;" :: "n"(n) : "memory")

// ---------------------------------------------------------------------------
// GroupNorm: one block per (batch, group). group = 16 channels x 2048 T.
// ---------------------------------------------------------------------------
__global__ void __launch_bounds__(256) gn_kernel(const float* __restrict__ x,
                                                 const float* __restrict__ gamma,
                                                 const float* __restrict__ beta,
                                                 float* __restrict__ y)
{
    __shared__ float rs[256], rq[256];
    const int bg = blockIdx.x;
    const int b = bg >> 5, g = bg & 31;
    const size_t base = ((size_t)b * NC + g * 16) * NT;
    const int n = 16 * NT;

    float s = 0.f, q = 0.f;
    for (int i = threadIdx.x * 4; i < n; i += 256 * 4) {
        float4 v = *(const float4*)(x + base + i);
        s += v.x + v.y + v.z + v.w;
        q += v.x * v.x + v.y * v.y + v.z * v.z + v.w * v.w;
    }
    rs[threadIdx.x] = s; rq[threadIdx.x] = q;
    __syncthreads();
    for (int off = 128; off > 0; off >>= 1) {
        if (threadIdx.x < off) {
            rs[threadIdx.x] += rs[threadIdx.x + off];
            rq[threadIdx.x] += rq[threadIdx.x + off];
        }
        __syncthreads();
    }
    const float mean = rs[0] / (float)n;
    const float var  = rq[0] / (float)n - mean * mean;
    const float inv  = rsqrtf(var + 1e-5f);

    for (int i = threadIdx.x * 4; i < n; i += 256 * 4) {
        const int c = g * 16 + (i >> 11);
        const float ga = gamma[c], be = beta[c];
        float4 v = *(const float4*)(x + base + i);
        float4 o;
        o.x = (v.x - mean) * inv * ga + be;
        o.y = (v.y - mean) * inv * ga + be;
        o.z = (v.z - mean) * inv * ga + be;
        o.w = (v.w - mean) * inv * ga + be;
        *(float4*)(y + base + i) = o;
    }
}

// ---------------------------------------------------------------------------
// tf32 mma.sync GEMM: C = W[M,K=512] @ X[b][K,N] (+bias, routed epilogue).
// MODE 0: proj  -> out = C + bias + res (fp32)
// MODE 1: qkv   -> tf32-rounded, INTERLEAVED layouts for attention:
//   Q [bh][t][c]: channels within 8-group at positions (0,4,1,5,2,6,3,7)
//   K [bh][t][c]: channel-perm AND key(t)-perm within 8-groups
//   V [bh][c][t]: key(t)-perm within 8-groups
// (source-permuted reads from smem; global stores stay coalesced float4)
// ---------------------------------------------------------------------------
#define AST 17
#define CST 132

template <int MODE>
__global__ void __launch_bounds__(256) tf32_gemm_kernel(
    const float* __restrict__ W, const float* __restrict__ X,
    const float* __restrict__ bias, const float* __restrict__ res,
    float* __restrict__ Co, float* __restrict__ Ko, float* __restrict__ Vo)
{
    extern __shared__ char smraw[];
    uint32_t* As = (uint32_t*)smraw;            // [128][AST]
    uint32_t* Bs = As + 128 * AST;              // [128][AST]
    float*    Cst = (float*)smraw;              // [128][CST] (epilogue alias)

    const int K = NC, N = NT;
    const int batch = blockIdx.z;
    const float* Xb = X + (size_t)batch * K * N;

    const int tid = threadIdx.x;
    const int w = tid >> 5, lane = tid & 31;
    const int g = lane >> 2, qd = lane & 3;
    const int wm = w >> 1, wn = w & 1;
    const int m0 = blockIdx.y * 128;
    const int n0 = blockIdx.x * 128;

    float acc[2][8][4] = {};

    for (int k0 = 0; k0 < K; k0 += 16) {
        {
            const int row = tid >> 1;
            const int f0 = (tid & 1) * 8;
            const float* src = W + (size_t)(m0 + row) * K + k0 + f0;
            float4 v0 = *(const float4*)(src);
            float4 v1 = *(const float4*)(src + 4);
            uint32_t* d = As + row * AST + f0;
            d[0] = cvt_tf32(v0.x); d[1] = cvt_tf32(v0.y);
            d[2] = cvt_tf32(v0.z); d[3] = cvt_tf32(v0.w);
            d[4] = cvt_tf32(v1.x); d[5] = cvt_tf32(v1.y);
            d[6] = cvt_tf32(v1.z); d[7] = cvt_tf32(v1.w);
        }
        {
            const int kk = tid >> 4;
            const int nb = (tid & 15) * 8;
            const float* src = Xb + (size_t)(k0 + kk) * N + n0 + nb;
            float4 v0 = *(const float4*)(src);
            float4 v1 = *(const float4*)(src + 4);
            uint32_t* d = Bs + nb * AST + kk;
            d[0 * AST] = cvt_tf32(v0.x); d[1 * AST] = cvt_tf32(v0.y);
            d[2 * AST] = cvt_tf32(v0.z); d[3 * AST] = cvt_tf32(v0.w);
            d[4 * AST] = cvt_tf32(v1.x); d[5 * AST] = cvt_tf32(v1.y);
            d[6 * AST] = cvt_tf32(v1.z); d[7 * AST] = cvt_tf32(v1.w);
        }
        __syncthreads();

#pragma unroll
        for (int ks = 0; ks < 2; ks++) {
            uint32_t av[2][4];
#pragma unroll
            for (int mt = 0; mt < 2; mt++) {
                const uint32_t* a0 = As + (wm * 32 + mt * 16 + g) * AST + ks * 8 + qd;
                const uint32_t* a1 = a0 + 8 * AST;
                av[mt][0] = a0[0]; av[mt][1] = a1[0];
                av[mt][2] = a0[4]; av[mt][3] = a1[4];
            }
#pragma unroll
            for (int nt = 0; nt < 8; nt++) {
                const uint32_t* bp = Bs + (wn * 64 + nt * 8 + g) * AST + ks * 8 + qd;
                const uint32_t b0 = bp[0], b1 = bp[4];
                mma8(acc[0][nt], av[0], b0, b1);
                mma8(acc[1][nt], av[1], b0, b1);
            }
        }
        __syncthreads();
    }

#pragma unroll
    for (int mt = 0; mt < 2; mt++)
#pragma unroll
        for (int nt = 0; nt < 8; nt++) {
            float* c0 = Cst + (wm * 32 + mt * 16 + g) * CST + wn * 64 + nt * 8 + 2 * qd;
            c0[0] = acc[mt][nt][0];
            c0[1] = acc[mt][nt][1];
            c0[8 * CST] = acc[mt][nt][2];
            c0[8 * CST + 1] = acc[mt][nt][3];
        }
    __syncthreads();

    if (MODE == 0) {
#pragma unroll
        for (int i = 0; i < 16; i++) {
            const int idx = tid + i * 256;
            const int m = idx >> 5, t4 = (idx & 31) * 4;
            const float bv = bias[m0 + m];
            float4 c = *(const float4*)(Cst + m * CST + t4);
            const size_t go = ((size_t)batch * NC + m0 + m) * NT + n0 + t4;
            float4 r = *(const float4*)(res + go);
            c.x += bv + r.x; c.y += bv + r.y; c.z += bv + r.z; c.w += bv + r.w;
            *(float4*)(Co + go) = c;
        }
    } else {
#pragma unroll
        for (int hh = 0; hh < 2; hh++) {
            const int mbase = m0 + hh * 64;
            const int h = mbase / 192;
            const int r = mbase % 192;
            const int seg = r >> 6;                 // 0=q 1=k 2=v
            const int bh = batch * NH + h;
            if (seg == 2) {
                // V: [bh][c][t], t positions hold keys interleaved within 8-groups
#pragma unroll
                for (int i = 0; i < 8; i++) {
                    const int idx = tid + i * 256;
                    const int c = idx >> 5, t4 = (idx & 31) * 4;
                    const float bv = bias[mbase + c];
                    const float* s = Cst + (hh * 64 + c) * CST;
                    const int tb = t4 & ~7, o = t4 & 4;
                    const int k0 = tb + (o ? 2 : 0), k1 = tb + (o ? 6 : 4);
                    const int k2 = tb + (o ? 3 : 1), k3 = tb + (o ? 7 : 5);
                    float4 v;
                    v.x = tf32f(s[k0] + bv); v.y = tf32f(s[k1] + bv);
                    v.z = tf32f(s[k2] + bv); v.w = tf32f(s[k3] + bv);
                    *(float4*)(Vo + ((size_t)bh * CH + c) * NT + n0 + t4) = v;
                }
            } else {
                // Q/K: [bh][t][c], channel positions interleaved; K rows (t) also
                // hold keys interleaved within 8-groups. Q scaled by 1/8.
                const float sc = (seg == 0) ? 0.125f : 1.0f;
                float* dst = (seg ? Ko : Co) + (size_t)bh * NT * CH;
#pragma unroll
                for (int i = 0; i < 8; i++) {
                    const int idx = tid + i * 256;
                    const int t = idx >> 4, cc = (idx & 15) * 4;
                    const int tt = seg ? ((t & ~7) + ((t & 1) ? ((t & 7) >> 1) + 4
                                                             : ((t & 7) >> 1)))
                                       : t;
                    const int cb = cc & ~7, o = cc & 4;
                    const int c0 = cb + (o ? 2 : 0), c1 = cb + (o ? 6 : 4);
                    const int c2 = cb + (o ? 3 : 1), c3 = cb + (o ? 7 : 5);
                    float4 v;
                    v.x = tf32f((Cst[(hh * 64 + c0) * CST + tt] + bias[mbase + c0]) * sc);
                    v.y = tf32f((Cst[(hh * 64 + c1) * CST + tt] + bias[mbase + c1]) * sc);
                    v.z = tf32f((Cst[(hh * 64 + c2) * CST + tt] + bias[mbase + c2]) * sc);
                    v.w = tf32f((Cst[(hh * 64 + c3) * CST + tt] + bias[mbase + c3]) * sc);
                    *(float4*)(dst + (size_t)(n0 + t) * CH + cc) = v;
                }
            }
        }
    }
}

#define GEMM_SMEM (128 * CST * 4)

// ---------------------------------------------------------------------------
// tf32 mma.sync flash attention, shuffle-free: second GEMM computes
// O^T = V @ P^T; interleaved layouts make the exp'd S C-frags directly usable
// as B-frags and all smem fragment loads single LDS.64 (stride 72 = 8 mod 32,
// conflict-free). 4 warps x 32 queries = 128-query CTA, cp.async
// double-buffered 64-key tiles.
// ---------------------------------------------------------------------------
#define SQ 72
#define SV 72
#define QS_OFF 0u
#define K0_OFF 36864u
#define K1_OFF 55296u
#define V0_OFF 73728u
#define V1_OFF 92160u
#define LS_OFF 110592u
#define ATT_SMEM (LS_OFF + 640u)
#define OST 132
#define NTILE 32
#define L2E 1.4426950408889634f

__global__ void __launch_bounds__(128, 2) attn_mma_kernel(const float* __restrict__ Qg_,
                                                          const float* __restrict__ Kg_,
                                                          const float* __restrict__ Vg_,
                                                          float* __restrict__ out)
{
    extern __shared__ char smem[];
    const uint32_t sb = smem_u32(smem);
    uint32_t* Qs  = (uint32_t*)(smem + QS_OFF);
    float*    Ls  = (float*)(smem + LS_OFF);
    float*    Osm = (float*)(smem + QS_OFF);     // epilogue reuse of Q area

    const int tid = threadIdx.x;
    const int w = tid >> 5, lane = tid & 31;
    const int g = lane >> 2, qd = lane & 3;
    const int bh = blockIdx.y;
    const int b = bh >> 3, h = bh & 7;
    const int t0 = blockIdx.x * 128;

    const float* Qg = Qg_ + ((size_t)bh * NT + t0) * CH;
    const float* Kg = Kg_ + (size_t)bh * NT * CH;
    const float* Vg = Vg_ + (size_t)bh * CH * NT;

    // fill coordinates: 16 threads per row, 16B each (128 threads -> 8 rows/pass)
    const int fr = tid >> 4, fc = (tid & 15) * 4;

    // prologue: Q (128 rows) + K/V tile0, tile1 (raw byte copies)
#pragma unroll
    for (int i = 0; i < 16; i++)
        cpa16(sb + QS_OFF + ((fr + i * 8) * SQ + fc) * 4,
              Qg + (size_t)(fr + i * 8) * CH + fc);
#pragma unroll
    for (int i = 0; i < 8; i++)
        cpa16(sb + K0_OFF + ((fr + i * 8) * SQ + fc) * 4,
              Kg + (size_t)(fr + i * 8) * CH + fc);
#pragma unroll
    for (int i = 0; i < 8; i++)
        cpa16(sb + V0_OFF + ((fr + i * 8) * SV + fc) * 4,
              Vg + (size_t)(fr + i * 8) * NT + fc);
    CP_COMMIT();
#pragma unroll
    for (int i = 0; i < 8; i++)
        cpa16(sb + K1_OFF + ((fr + i * 8) * SQ + fc) * 4,
              Kg + (size_t)(64 + fr + i * 8) * CH + fc);
#pragma unroll
    for (int i = 0; i < 8; i++)
        cpa16(sb + V1_OFF + ((fr + i * 8) * SV + fc) * 4,
              Vg + (size_t)(fr + i * 8) * NT + 64 + fc);
    CP_COMMIT();
    CP_WAIT(1);
    __syncthreads();

    // preload Q A-fragments (uint2: channel-interleaved layout)
    uint32_t qa[2][8][4];
#pragma unroll
    for (int mt = 0; mt < 2; mt++)
#pragma unroll
        for (int ks = 0; ks < 8; ks++) {
            uint2 lo = *(const uint2*)(Qs + (w * 32 + mt * 16 + g) * SQ + ks * 8 + 2 * qd);
            uint2 hi = *(const uint2*)(Qs + (w * 32 + mt * 16 + 8 + g) * SQ + ks * 8 + 2 * qd);
            qa[mt][ks][0] = lo.x; qa[mt][ks][1] = hi.x;
            qa[mt][ks][2] = lo.y; qa[mt][ks][3] = hi.y;
        }

    float oacc[4][4][4] = {};      // [ch-tile][q-tile][frag] : O^T
    float lr[2][2] = {};
    for (int st = 0; st < NTILE; st++) {
        const uint32_t* Ks = (const uint32_t*)(smem + ((st & 1) ? K1_OFF : K0_OFF));
        const uint32_t* Vs = (const uint32_t*)(smem + ((st & 1) ? V1_OFF : V0_OFF));

        // S = Q @ K^T  (columns come out key-interleaved by construction)
        float sacc[2][8][4] = {};
#pragma unroll
        for (int nt = 0; nt < 8; nt++) {
            const uint32_t* kr = Ks + (nt * 8 + g) * SQ + 2 * qd;
#pragma unroll
            for (int ks = 0; ks < 8; ks++) {
                uint2 bp = *(const uint2*)(kr + ks * 8);
                mma8(sacc[0][nt], qa[0][ks], bp.x, bp.y);
                mma8(sacc[1][nt], qa[1][ks], bp.x, bp.y);
            }
        }
        // softmax terms (no max subtraction) + tf32 P fragments
        uint32_t pc[2][8][4];
#pragma unroll
        for (int mt = 0; mt < 2; mt++)
#pragma unroll
            for (int nt = 0; nt < 8; nt++) {
                float p0 = ex2f(sacc[mt][nt][0] * L2E);
                float p1 = ex2f(sacc[mt][nt][1] * L2E);
                float p2 = ex2f(sacc[mt][nt][2] * L2E);
                float p3 = ex2f(sacc[mt][nt][3] * L2E);
                lr[mt][0] += p0 + p1;
                lr[mt][1] += p2 + p3;
                pc[mt][nt][0] = cvt_tf32(p0); pc[mt][nt][1] = cvt_tf32(p1);
                pc[mt][nt][2] = cvt_tf32(p2); pc[mt][nt][3] = cvt_tf32(p3);
            }
        // O^T += V @ P^T : pc registers ARE the B-frags; zero shuffles.
#pragma unroll
        for (int j = 0; j < 8; j++) {
            uint32_t va[4][4];
#pragma unroll
            for (int ct = 0; ct < 4; ct++) {
                uint2 lo = *(const uint2*)(Vs + (ct * 16 + g) * SV + j * 8 + 2 * qd);
                uint2 hi = *(const uint2*)(Vs + (ct * 16 + 8 + g) * SV + j * 8 + 2 * qd);
                va[ct][0] = lo.x; va[ct][1] = hi.x;
                va[ct][2] = lo.y; va[ct][3] = hi.y;
            }
#pragma unroll
            for (int ct = 0; ct < 4; ct++) {
                mma8(oacc[ct][0], va[ct], pc[0][j][0], pc[0][j][1]);
                mma8(oacc[ct][1], va[ct], pc[0][j][2], pc[0][j][3]);
                mma8(oacc[ct][2], va[ct], pc[1][j][0], pc[1][j][1]);
                mma8(oacc[ct][3], va[ct], pc[1][j][2], pc[1][j][3]);
            }
        }
        __syncthreads();   // done reading buf[st&1]

        if (st + 2 < NTILE) {
            const int s0 = (st + 2) * 64;
            const uint32_t ko = (st & 1) ? K1_OFF : K0_OFF;
            const uint32_t vo = (st & 1) ? V1_OFF : V0_OFF;
#pragma unroll
            for (int i = 0; i < 8; i++)
                cpa16(sb + ko + ((fr + i * 8) * SQ + fc) * 4,
                      Kg + (size_t)(s0 + fr + i * 8) * CH + fc);
#pragma unroll
            for (int i = 0; i < 8; i++)
                cpa16(sb + vo + ((fr + i * 8) * SV + fc) * 4,
                      Vg + (size_t)(fr + i * 8) * NT + s0 + fc);
            CP_COMMIT();
        }
        if (st + 1 < NTILE) {
            if (st + 2 < NTILE) { CP_WAIT(1); } else { CP_WAIT(0); }
            __syncthreads();
        }
    }

    // row-sum reduce across the 4 qd lanes; store inverse sums per query
#pragma unroll
    for (int mt = 0; mt < 2; mt++) {
        lr[mt][0] += __shfl_xor_sync(0xFFFFFFFFu, lr[mt][0], 1);
        lr[mt][0] += __shfl_xor_sync(0xFFFFFFFFu, lr[mt][0], 2);
        lr[mt][1] += __shfl_xor_sync(0xFFFFFFFFu, lr[mt][1], 1);
        lr[mt][1] += __shfl_xor_sync(0xFFFFFFFFu, lr[mt][1], 2);
        if (qd == 0) {
            Ls[w * 32 + mt * 16 + g]     = 1.0f / lr[mt][0];
            Ls[w * 32 + mt * 16 + 8 + g] = 1.0f / lr[mt][1];
        }
    }
    __syncthreads();   // Ls visible; Q smem free for O staging

    // normalize + stage O^T[ch][q] into reused Q area (stride OST)
#pragma unroll
    for (int ct = 0; ct < 4; ct++)
#pragma unroll
        for (int qt = 0; qt < 4; qt++) {
            const int q0 = w * 32 + qt * 8 + 2 * qd;
            const float i0 = Ls[q0], i1 = Ls[q0 + 1];
            float2 a; a.x = oacc[ct][qt][0] * i0; a.y = oacc[ct][qt][1] * i1;
            float2 c; c.x = oacc[ct][qt][2] * i0; c.y = oacc[ct][qt][3] * i1;
            *(float2*)(Osm + (ct * 16 + g) * OST + q0) = a;
            *(float2*)(Osm + (ct * 16 + 8 + g) * OST + q0) = c;
        }
    __syncthreads();

    // coalesced write: out[b][h*64+ch][t0 + q]
#pragma unroll
    for (int i = 0; i < 16; i++) {
        const int idx = tid + i * 128;
        const int ch = idx >> 5, q4 = (idx & 31) * 4;
        float4 wv = *(const float4*)(Osm + ch * OST + q4);
        *(float4*)(out + ((size_t)b * NC + h * CH + ch) * NT + t0 + q4) = wv;
    }
}

// ---------------------------------------------------------------------------
extern "C" void kernel_launch(void* const* d_in, const int* in_sizes, int n_in,
                              void* d_out, int out_size)
{
    const float* x     = (const float*)d_in[0];
    const float* g1g   = (const float*)d_in[1];
    const float* g1b   = (const float*)d_in[2];
    const float* wqkv  = (const float*)d_in[3];
    const float* bqkv  = (const float*)d_in[4];
    const float* g2g   = (const float*)d_in[5];
    const float* g2b   = (const float*)d_in[6];
    const float* wproj = (const float*)d_in[7];
    const float* bproj = (const float*)d_in[8];
    float* out = (float*)d_out;

    float *xn, *q, *k, *v, *attn, *an;
    cudaGetSymbolAddress((void**)&xn,   g_xn);
    cudaGetSymbolAddress((void**)&q,    g_q);
    cudaGetSymbolAddress((void**)&k,    g_k);
    cudaGetSymbolAddress((void**)&v,    g_v);
    cudaGetSymbolAddress((void**)&attn, g_attn);
    cudaGetSymbolAddress((void**)&an,   g_an);

    cudaFuncSetAttribute(tf32_gemm_kernel<0>,
                         cudaFuncAttributeMaxDynamicSharedMemorySize, GEMM_SMEM);
    cudaFuncSetAttribute(tf32_gemm_kernel<1>,
                         cudaFuncAttributeMaxDynamicSharedMemorySize, GEMM_SMEM);
    cudaFuncSetAttribute(attn_mma_kernel,
                         cudaFuncAttributeMaxDynamicSharedMemorySize, ATT_SMEM);

    // 1) GroupNorm 1
    gn_kernel<<<NB * NGRP, 256>>>(x, g1g, g1b, xn);

    // 2) QKV conv1x1 (tf32 tensor) with interleaved-layout routing epilogue
    tf32_gemm_kernel<1><<<dim3(NT / 128, 12, NB), 256, GEMM_SMEM>>>(
        wqkv, xn, bqkv, nullptr, q, k, v);

    // 3) tf32 mma.sync flash attention (shuffle-free O^T formulation)
    attn_mma_kernel<<<dim3(NT / 128, NB * NH), 128, ATT_SMEM>>>(q, k, v, attn);

    // 4) GroupNorm 2
    gn_kernel<<<NB * NGRP, 256>>>(attn, g2g, g2b, an);

    // 5) proj conv1x1 (tf32 tensor) + bias + residual
    tf32_gemm_kernel<0><<<dim3(NT / 128, 4, NB), 256, GEMM_SMEM>>>(
        wproj, an, bproj, x, out, nullptr, nullptr);
}

// round 17
// speedup vs baseline: 1.2188x; 1.1689x over previous
#include <cuda_runtime.h>
#include <cstdint>
#include <math.h>

#define NB 8
#define NC 512
#define NT 2048
#define NGRP 32
#define NH 8
#define CH 64

// scratch (no cudaMalloc allowed)
__device__ float g_xn[NB * NC * NT];            // 32 MB (tf32-rounded)
__device__ float g_q[NB * NH * NT * CH];        // 32 MB  [b,h,t,c] tf32, ch-perm
__device__ float g_k[NB * NH * NT * CH];        // 32 MB  [b,h,t,c] tf32, ch+key-perm
__device__ float g_v[NB * NH * CH * NT];        // 32 MB  [b,h,c,t] tf32, key-perm
__device__ float g_attn[NB * NC * NT];          // 32 MB  [b,c,t]
__device__ float g_an[NB * NC * NT];            // 32 MB (tf32-rounded)
__device__ float g_w32[3 * NC * NC + NC * NC];  // 4 MB  tf32-rounded weights

// ---------------------------------------------------------------------------
// helpers
// ---------------------------------------------------------------------------
__device__ __forceinline__ uint32_t cvt_tf32(float f) {
    uint32_t u;
    asm("cvt.rna.tf32.f32 %0, %1;" : "=r"(u) : "f"(f));
    return u;
}
__device__ __forceinline__ float tf32f(float f) {
    return __uint_as_float(cvt_tf32(f));
}
__device__ __forceinline__ float ex2f(float x) {
    float r;
    asm("ex2.approx.ftz.f32 %0, %1;" : "=f"(r) : "f"(x));
    return r;
}
// D += A @ B  (m16n8k8 tf32)
__device__ __forceinline__ void mma8(float* d, const uint32_t* a, uint32_t b0, uint32_t b1) {
    asm volatile(
        "mma.sync.aligned.m16n8k8.row.col.f32.tf32.tf32.f32 "
        "{%0,%1,%2,%3}, {%4,%5,%6,%7}, {%8,%9}, {%0,%1,%2,%3};"
        : "+f"(d[0]), "+f"(d[1]), "+f"(d[2]), "+f"(d[3])
        : "r"(a[0]), "r"(a[1]), "r"(a[2]), "r"(a[3]), "r"(b0), "r"(b1));
}
__device__ __forceinline__ uint32_t smem_u32(const void* p) {
    uint32_t r;
    asm("{ .reg .u64 t; cvta.to.shared.u64 t, %1; cvt.u32.u64 %0, t; }"
        : "=r"(r) : "l"(p));
    return r;
}
__device__ __forceinline__ void cpa16(uint32_t s, const void* g) {
    asm volatile("cp.async.ca.shared.global [%0], [%1], 16;" :: "r"(s), "l"(g));
}
#define CP_COMMIT() asm volatile("cp.async.commit_group;" ::: "memory")
#define CP_WAIT(n)  asm volatile("cp.async.wait_group %0;" :: "n"(n) : "memory")

// ---------------------------------------------------------------------------
// Weight prep: tf32-round both weight matrices into g_w32.
// ---------------------------------------------------------------------------
__global__ void __launch_bounds__(256) prep_w_kernel(const float* __restrict__ wq,
                                                     const float* __restrict__ wp)
{
    const int nq = 3 * NC * NC;
    const int np = NC * NC;
    const int idx = (blockIdx.x * 256 + threadIdx.x) * 4;
    if (idx < nq) {
        float4 v = *(const float4*)(wq + idx);
        float4 o;
        o.x = tf32f(v.x); o.y = tf32f(v.y); o.z = tf32f(v.z); o.w = tf32f(v.w);
        *(float4*)(g_w32 + idx) = o;
    } else if (idx < nq + np) {
        const int j = idx - nq;
        float4 v = *(const float4*)(wp + j);
        float4 o;
        o.x = tf32f(v.x); o.y = tf32f(v.y); o.z = tf32f(v.z); o.w = tf32f(v.w);
        *(float4*)(g_w32 + idx) = o;
    }
}

// ---------------------------------------------------------------------------
// GroupNorm: one block per (batch, group); output tf32-rounded (feeds GEMM B).
// ---------------------------------------------------------------------------
__global__ void __launch_bounds__(256) gn_kernel(const float* __restrict__ x,
                                                 const float* __restrict__ gamma,
                                                 const float* __restrict__ beta,
                                                 float* __restrict__ y)
{
    __shared__ float rs[256], rq[256];
    const int bg = blockIdx.x;
    const int b = bg >> 5, g = bg & 31;
    const size_t base = ((size_t)b * NC + g * 16) * NT;
    const int n = 16 * NT;

    float s = 0.f, q = 0.f;
    for (int i = threadIdx.x * 4; i < n; i += 256 * 4) {
        float4 v = *(const float4*)(x + base + i);
        s += v.x + v.y + v.z + v.w;
        q += v.x * v.x + v.y * v.y + v.z * v.z + v.w * v.w;
    }
    rs[threadIdx.x] = s; rq[threadIdx.x] = q;
    __syncthreads();
    for (int off = 128; off > 0; off >>= 1) {
        if (threadIdx.x < off) {
            rs[threadIdx.x] += rs[threadIdx.x + off];
            rq[threadIdx.x] += rq[threadIdx.x + off];
        }
        __syncthreads();
    }
    const float mean = rs[0] / (float)n;
    const float var  = rq[0] / (float)n - mean * mean;
    const float inv  = rsqrtf(var + 1e-5f);

    for (int i = threadIdx.x * 4; i < n; i += 256 * 4) {
        const int c = g * 16 + (i >> 11);
        const float ga = gamma[c], be = beta[c];
        float4 v = *(const float4*)(x + base + i);
        float4 o;
        o.x = tf32f((v.x - mean) * inv * ga + be);
        o.y = tf32f((v.y - mean) * inv * ga + be);
        o.z = tf32f((v.z - mean) * inv * ga + be);
        o.w = tf32f((v.w - mean) * inv * ga + be);
        *(float4*)(y + base + i) = o;
    }
}

// ---------------------------------------------------------------------------
// tf32 mma.sync GEMM, cp.async double-buffered (operands pre-rounded tf32).
// A [m][k] stride 20 floats; B [k][n] stride 136 floats (both conflict-free).
// MODE 0: proj  -> out = C + bias + res (fp32)
// MODE 1: qkv   -> interleaved tf32 Q/K/V layouts (same as R16)
// ---------------------------------------------------------------------------
#define A_ST 20
#define B_ST 136
#define ABUF 10240u
#define BBUF 8704u
#define BUFSZ (ABUF + BBUF)
#define CST 132
#define GEMM_SMEM (128 * CST * 4)

template <int MODE>
__global__ void __launch_bounds__(256) tf32_gemm_kernel(
    const float* __restrict__ W, const float* __restrict__ X,
    const float* __restrict__ bias, const float* __restrict__ res,
    float* __restrict__ Co, float* __restrict__ Ko, float* __restrict__ Vo)
{
    extern __shared__ char smraw[];
    const uint32_t sb = smem_u32(smraw);
    float* Cst = (float*)smraw;                 // epilogue alias over buffers

    const int K = NC, N = NT;
    const int batch = blockIdx.z;
    const float* Xb = X + (size_t)batch * K * N;

    const int tid = threadIdx.x;
    const int w = tid >> 5, lane = tid & 31;
    const int g = lane >> 2, qd = lane & 3;
    const int wm = w >> 1, wn = w & 1;
    const int m0 = blockIdx.y * 128;
    const int n0 = blockIdx.x * 128;

    // per-thread fill coordinates
    const int arow = tid >> 1, ahalf = tid & 1;        // A: 2x cpa16 (32B) per thread
    const int bch = tid * 2;                           // B: chunks of 16B

    // fill one (A,B) tile pair into buffer `buf` for k-offset k0
    auto fill = [&](int buf, int k0) {
        const uint32_t sbuf = sb + buf * BUFSZ;
        const float* asrc = W + (size_t)(m0 + arow) * K + k0 + ahalf * 8;
        const uint32_t adst = sbuf + (uint32_t)(arow * A_ST + ahalf * 8) * 4u;
        cpa16(adst, asrc);
        cpa16(adst + 16, asrc + 4);
        const int brow = bch >> 5, bc16 = bch & 31;
        const float* bsrc = Xb + (size_t)(k0 + brow) * N + n0 + bc16 * 4;
        const uint32_t bdst = sbuf + ABUF + (uint32_t)(brow * B_ST + bc16 * 4) * 4u;
        cpa16(bdst, bsrc);
        cpa16(bdst + 16, bsrc + 4);
    };

    float acc[2][8][4] = {};

    fill(0, 0);  CP_COMMIT();
    fill(1, 16); CP_COMMIT();

    for (int kt = 0; kt < 32; kt++) {
        if (kt == 31) { CP_WAIT(0); } else { CP_WAIT(1); }
        __syncthreads();
        const uint32_t* As = (const uint32_t*)(smraw + (kt & 1) * BUFSZ);
        const uint32_t* Bs = (const uint32_t*)(smraw + (kt & 1) * BUFSZ + ABUF);

#pragma unroll
        for (int ks = 0; ks < 2; ks++) {
            uint32_t av[2][4];
#pragma unroll
            for (int mt = 0; mt < 2; mt++) {
                const uint32_t* a0 = As + (wm * 32 + mt * 16 + g) * A_ST + ks * 8 + qd;
                av[mt][0] = a0[0];
                av[mt][1] = a0[8 * A_ST];
                av[mt][2] = a0[4];
                av[mt][3] = a0[8 * A_ST + 4];
            }
#pragma unroll
            for (int nt = 0; nt < 8; nt++) {
                const uint32_t* bp = Bs + (ks * 8 + qd) * B_ST + wn * 64 + nt * 8 + g;
                const uint32_t b0 = bp[0], b1 = bp[4 * B_ST];
                mma8(acc[0][nt], av[0], b0, b1);
                mma8(acc[1][nt], av[1], b0, b1);
            }
        }
        __syncthreads();
        if (kt + 2 < 32) { fill(kt & 1, (kt + 2) * 16); CP_COMMIT(); }
    }

    // stage C into smem (aliased over buffers; guarded by syncthreads above)
#pragma unroll
    for (int mt = 0; mt < 2; mt++)
#pragma unroll
        for (int nt = 0; nt < 8; nt++) {
            float* c0 = Cst + (wm * 32 + mt * 16 + g) * CST + wn * 64 + nt * 8 + 2 * qd;
            c0[0] = acc[mt][nt][0];
            c0[1] = acc[mt][nt][1];
            c0[8 * CST] = acc[mt][nt][2];
            c0[8 * CST + 1] = acc[mt][nt][3];
        }
    __syncthreads();

    if (MODE == 0) {
#pragma unroll
        for (int i = 0; i < 16; i++) {
            const int idx = tid + i * 256;
            const int m = idx >> 5, t4 = (idx & 31) * 4;
            const float bv = bias[m0 + m];
            float4 c = *(const float4*)(Cst + m * CST + t4);
            const size_t go = ((size_t)batch * NC + m0 + m) * NT + n0 + t4;
            float4 r = *(const float4*)(res + go);
            c.x += bv + r.x; c.y += bv + r.y; c.z += bv + r.z; c.w += bv + r.w;
            *(float4*)(Co + go) = c;
        }
    } else {
#pragma unroll
        for (int hh = 0; hh < 2; hh++) {
            const int mbase = m0 + hh * 64;
            const int h = mbase / 192;
            const int r = mbase % 192;
            const int seg = r >> 6;                 // 0=q 1=k 2=v
            const int bh = batch * NH + h;
            if (seg == 2) {
                // V: [bh][c][t], t positions hold keys interleaved within 8-groups
#pragma unroll
                for (int i = 0; i < 8; i++) {
                    const int idx = tid + i * 256;
                    const int c = idx >> 5, t4 = (idx & 31) * 4;
                    const float bv = bias[mbase + c];
                    const float* s = Cst + (hh * 64 + c) * CST;
                    const int tb = t4 & ~7, o = t4 & 4;
                    const int k0 = tb + (o ? 2 : 0), k1 = tb + (o ? 6 : 4);
                    const int k2 = tb + (o ? 3 : 1), k3 = tb + (o ? 7 : 5);
                    float4 v;
                    v.x = tf32f(s[k0] + bv); v.y = tf32f(s[k1] + bv);
                    v.z = tf32f(s[k2] + bv); v.w = tf32f(s[k3] + bv);
                    *(float4*)(Vo + ((size_t)bh * CH + c) * NT + n0 + t4) = v;
                }
            } else {
                // Q/K: [bh][t][c], channels interleaved; K rows (t) also key-interleaved
                const float sc = (seg == 0) ? 0.125f : 1.0f;
                float* dst = (seg ? Ko : Co) + (size_t)bh * NT * CH;
#pragma unroll
                for (int i = 0; i < 8; i++) {
                    const int idx = tid + i * 256;
                    const int t = idx >> 4, cc = (idx & 15) * 4;
                    const int tt = seg ? ((t & ~7) + ((t & 1) ? ((t & 7) >> 1) + 4
                                                             : ((t & 7) >> 1)))
                                       : t;
                    const int cb = cc & ~7, o = cc & 4;
                    const int c0 = cb + (o ? 2 : 0), c1 = cb + (o ? 6 : 4);
                    const int c2 = cb + (o ? 3 : 1), c3 = cb + (o ? 7 : 5);
                    float4 v;
                    v.x = tf32f((Cst[(hh * 64 + c0) * CST + tt] + bias[mbase + c0]) * sc);
                    v.y = tf32f((Cst[(hh * 64 + c1) * CST + tt] + bias[mbase + c1]) * sc);
                    v.z = tf32f((Cst[(hh * 64 + c2) * CST + tt] + bias[mbase + c2]) * sc);
                    v.w = tf32f((Cst[(hh * 64 + c3) * CST + tt] + bias[mbase + c3]) * sc);
                    *(float4*)(dst + (size_t)(n0 + t) * CH + cc) = v;
                }
            }
        }
    }
}

// ---------------------------------------------------------------------------
// tf32 mma.sync flash attention (unchanged from R16): shuffle-free O^T = V @ P^T,
// interleaved layouts, LDS.64 fragment loads, cp.async double-buffered tiles.
// ---------------------------------------------------------------------------
#define SQ 72
#define SV 72
#define QS_OFF 0u
#define K0_OFF 36864u
#define K1_OFF 55296u
#define V0_OFF 73728u
#define V1_OFF 92160u
#define LS_OFF 110592u
#define ATT_SMEM (LS_OFF + 640u)
#define OST 132
#define NTILE 32
#define L2E 1.4426950408889634f

__global__ void __launch_bounds__(128, 2) attn_mma_kernel(const float* __restrict__ Qg_,
                                                          const float* __restrict__ Kg_,
                                                          const float* __restrict__ Vg_,
                                                          float* __restrict__ out)
{
    extern __shared__ char smem[];
    const uint32_t sb = smem_u32(smem);
    uint32_t* Qs  = (uint32_t*)(smem + QS_OFF);
    float*    Ls  = (float*)(smem + LS_OFF);
    float*    Osm = (float*)(smem + QS_OFF);     // epilogue reuse of Q area

    const int tid = threadIdx.x;
    const int w = tid >> 5, lane = tid & 31;
    const int g = lane >> 2, qd = lane & 3;
    const int bh = blockIdx.y;
    const int b = bh >> 3, h = bh & 7;
    const int t0 = blockIdx.x * 128;

    const float* Qg = Qg_ + ((size_t)bh * NT + t0) * CH;
    const float* Kg = Kg_ + (size_t)bh * NT * CH;
    const float* Vg = Vg_ + (size_t)bh * CH * NT;

    const int fr = tid >> 4, fc = (tid & 15) * 4;

#pragma unroll
    for (int i = 0; i < 16; i++)
        cpa16(sb + QS_OFF + ((fr + i * 8) * SQ + fc) * 4,
              Qg + (size_t)(fr + i * 8) * CH + fc);
#pragma unroll
    for (int i = 0; i < 8; i++)
        cpa16(sb + K0_OFF + ((fr + i * 8) * SQ + fc) * 4,
              Kg + (size_t)(fr + i * 8) * CH + fc);
#pragma unroll
    for (int i = 0; i < 8; i++)
        cpa16(sb + V0_OFF + ((fr + i * 8) * SV + fc) * 4,
              Vg + (size_t)(fr + i * 8) * NT + fc);
    CP_COMMIT();
#pragma unroll
    for (int i = 0; i < 8; i++)
        cpa16(sb + K1_OFF + ((fr + i * 8) * SQ + fc) * 4,
              Kg + (size_t)(64 + fr + i * 8) * CH + fc);
#pragma unroll
    for (int i = 0; i < 8; i++)
        cpa16(sb + V1_OFF + ((fr + i * 8) * SV + fc) * 4,
              Vg + (size_t)(fr + i * 8) * NT + 64 + fc);
    CP_COMMIT();
    CP_WAIT(1);
    __syncthreads();

    uint32_t qa[2][8][4];
#pragma unroll
    for (int mt = 0; mt < 2; mt++)
#pragma unroll
        for (int ks = 0; ks < 8; ks++) {
            uint2 lo = *(const uint2*)(Qs + (w * 32 + mt * 16 + g) * SQ + ks * 8 + 2 * qd);
            uint2 hi = *(const uint2*)(Qs + (w * 32 + mt * 16 + 8 + g) * SQ + ks * 8 + 2 * qd);
            qa[mt][ks][0] = lo.x; qa[mt][ks][1] = hi.x;
            qa[mt][ks][2] = lo.y; qa[mt][ks][3] = hi.y;
        }

    float oacc[4][4][4] = {};
    float lr[2][2] = {};
    for (int st = 0; st < NTILE; st++) {
        const uint32_t* Ks = (const uint32_t*)(smem + ((st & 1) ? K1_OFF : K0_OFF));
        const uint32_t* Vs = (const uint32_t*)(smem + ((st & 1) ? V1_OFF : V0_OFF));

        float sacc[2][8][4] = {};
#pragma unroll
        for (int nt = 0; nt < 8; nt++) {
            const uint32_t* kr = Ks + (nt * 8 + g) * SQ + 2 * qd;
#pragma unroll
            for (int ks = 0; ks < 8; ks++) {
                uint2 bp = *(const uint2*)(kr + ks * 8);
                mma8(sacc[0][nt], qa[0][ks], bp.x, bp.y);
                mma8(sacc[1][nt], qa[1][ks], bp.x, bp.y);
            }
        }
        uint32_t pc[2][8][4];
#pragma unroll
        for (int mt = 0; mt < 2; mt++)
#pragma unroll
            for (int nt = 0; nt < 8; nt++) {
                float p0 = ex2f(sacc[mt][nt][0] * L2E);
                float p1 = ex2f(sacc[mt][nt][1] * L2E);
                float p2 = ex2f(sacc[mt][nt][2] * L2E);
                float p3 = ex2f(sacc[mt][nt][3] * L2E);
                lr[mt][0] += p0 + p1;
                lr[mt][1] += p2 + p3;
                pc[mt][nt][0] = cvt_tf32(p0); pc[mt][nt][1] = cvt_tf32(p1);
                pc[mt][nt][2] = cvt_tf32(p2); pc[mt][nt][3] = cvt_tf32(p3);
            }
#pragma unroll
        for (int j = 0; j < 8; j++) {
            uint32_t va[4][4];
#pragma unroll
            for (int ct = 0; ct < 4; ct++) {
                uint2 lo = *(const uint2*)(Vs + (ct * 16 + g) * SV + j * 8 + 2 * qd);
                uint2 hi = *(const uint2*)(Vs + (ct * 16 + 8 + g) * SV + j * 8 + 2 * qd);
                va[ct][0] = lo.x; va[ct][1] = hi.x;
                va[ct][2] = lo.y; va[ct][3] = hi.y;
            }
#pragma unroll
            for (int ct = 0; ct < 4; ct++) {
                mma8(oacc[ct][0], va[ct], pc[0][j][0], pc[0][j][1]);
                mma8(oacc[ct][1], va[ct], pc[0][j][2], pc[0][j][3]);
                mma8(oacc[ct][2], va[ct], pc[1][j][0], pc[1][j][1]);
                mma8(oacc[ct][3], va[ct], pc[1][j][2], pc[1][j][3]);
            }
        }
        __syncthreads();

        if (st + 2 < NTILE) {
            const int s0 = (st + 2) * 64;
            const uint32_t ko = (st & 1) ? K1_OFF : K0_OFF;
            const uint32_t vo = (st & 1) ? V1_OFF : V0_OFF;
#pragma unroll
            for (int i = 0; i < 8; i++)
                cpa16(sb + ko + ((fr + i * 8) * SQ + fc) * 4,
                      Kg + (size_t)(s0 + fr + i * 8) * CH + fc);
#pragma unroll
            for (int i = 0; i < 8; i++)
                cpa16(sb + vo + ((fr + i * 8) * SV + fc) * 4,
                      Vg + (size_t)(fr + i * 8) * NT + s0 + fc);
            CP_COMMIT();
        }
        if (st + 1 < NTILE) {
            if (st + 2 < NTILE) { CP_WAIT(1); } else { CP_WAIT(0); }
            __syncthreads();
        }
    }

#pragma unroll
    for (int mt = 0; mt < 2; mt++) {
        lr[mt][0] += __shfl_xor_sync(0xFFFFFFFFu, lr[mt][0], 1);
        lr[mt][0] += __shfl_xor_sync(0xFFFFFFFFu, lr[mt][0], 2);
        lr[mt][1] += __shfl_xor_sync(0xFFFFFFFFu, lr[mt][1], 1);
        lr[mt][1] += __shfl_xor_sync(0xFFFFFFFFu, lr[mt][1], 2);
        if (qd == 0) {
            Ls[w * 32 + mt * 16 + g]     = 1.0f / lr[mt][0];
            Ls[w * 32 + mt * 16 + 8 + g] = 1.0f / lr[mt][1];
        }
    }
    __syncthreads();

#pragma unroll
    for (int ct = 0; ct < 4; ct++)
#pragma unroll
        for (int qt = 0; qt < 4; qt++) {
            const int q0 = w * 32 + qt * 8 + 2 * qd;
            const float i0 = Ls[q0], i1 = Ls[q0 + 1];
            float2 a; a.x = oacc[ct][qt][0] * i0; a.y = oacc[ct][qt][1] * i1;
            float2 c; c.x = oacc[ct][qt][2] * i0; c.y = oacc[ct][qt][3] * i1;
            *(float2*)(Osm + (ct * 16 + g) * OST + q0) = a;
            *(float2*)(Osm + (ct * 16 + 8 + g) * OST + q0) = c;
        }
    __syncthreads();

#pragma unroll
    for (int i = 0; i < 16; i++) {
        const int idx = tid + i * 128;
        const int ch = idx >> 5, q4 = (idx & 31) * 4;
        float4 wv = *(const float4*)(Osm + ch * OST + q4);
        *(float4*)(out + ((size_t)b * NC + h * CH + ch) * NT + t0 + q4) = wv;
    }
}

// ---------------------------------------------------------------------------
extern "C" void kernel_launch(void* const* d_in, const int* in_sizes, int n_in,
                              void* d_out, int out_size)
{
    const float* x     = (const float*)d_in[0];
    const float* g1g   = (const float*)d_in[1];
    const float* g1b   = (const float*)d_in[2];
    const float* wqkv  = (const float*)d_in[3];
    const float* bqkv  = (const float*)d_in[4];
    const float* g2g   = (const float*)d_in[5];
    const float* g2b   = (const float*)d_in[6];
    const float* wproj = (const float*)d_in[7];
    const float* bproj = (const float*)d_in[8];
    float* out = (float*)d_out;

    float *xn, *q, *k, *v, *attn, *an, *w32;
    cudaGetSymbolAddress((void**)&xn,   g_xn);
    cudaGetSymbolAddress((void**)&q,    g_q);
    cudaGetSymbolAddress((void**)&k,    g_k);
    cudaGetSymbolAddress((void**)&v,    g_v);
    cudaGetSymbolAddress((void**)&attn, g_attn);
    cudaGetSymbolAddress((void**)&an,   g_an);
    cudaGetSymbolAddress((void**)&w32,  g_w32);

    cudaFuncSetAttribute(tf32_gemm_kernel<0>,
                         cudaFuncAttributeMaxDynamicSharedMemorySize, GEMM_SMEM);
    cudaFuncSetAttribute(tf32_gemm_kernel<1>,
                         cudaFuncAttributeMaxDynamicSharedMemorySize, GEMM_SMEM);
    cudaFuncSetAttribute(attn_mma_kernel,
                         cudaFuncAttributeMaxDynamicSharedMemorySize, ATT_SMEM);

    // 0) tf32-round weights
    prep_w_kernel<<<(3 * NC * NC + NC * NC) / 1024, 256>>>(wqkv, wproj);

    // 1) GroupNorm 1 (tf32-rounded output)
    gn_kernel<<<NB * NGRP, 256>>>(x, g1g, g1b, xn);

    // 2) QKV conv1x1 (pipelined tf32 tensor) with interleaved routing epilogue
    tf32_gemm_kernel<1><<<dim3(NT / 128, 12, NB), 256, GEMM_SMEM>>>(
        w32, xn, bqkv, nullptr, q, k, v);

    // 3) tf32 mma.sync flash attention (shuffle-free O^T formulation)
    attn_mma_kernel<<<dim3(NT / 128, NB * NH), 128, ATT_SMEM>>>(q, k, v, attn);

    // 4) GroupNorm 2 (tf32-rounded output)
    gn_kernel<<<NB * NGRP, 256>>>(attn, g2g, g2b, an);

    // 5) proj conv1x1 (pipelined tf32 tensor) + bias + residual
    tf32_gemm_kernel<0><<<dim3(NT / 128, 4, NB), 256, GEMM_SMEM>>>(
        w32 + 3 * NC * NC, an, bproj, x, out, nullptr, nullptr);
}